// round 15
// baseline (speedup 1.0000x reference)
#include <cuda_runtime.h>

#define N_ATOMS 6144
#define TILE_I  64
#define TILE_J  1024
#define THREADS 256

// Dense masked pairwise distance map.
// out[i*N + j] = sqrt(|r_i - r_j|^2)  if  i > j && species_i != -1 && species_j != -1
//                                         && sq > 0 && dist <= cutoff
//              = 0 otherwise.
//
// Tiling: each block covers TILE_I rows x TILE_J cols. 256 threads, each thread
// owns 4 consecutive j (one float4 store per row iteration -> coalesced 512B/warp).
// Tiles strictly above the diagonal are pure zero-fill (no math, no smem).
__global__ __launch_bounds__(THREADS)
void cell_list_kernel(const int*   __restrict__ species,
                      const float* __restrict__ coords,
                      const int*   __restrict__ cutoff_raw,
                      float*       __restrict__ out)
{
    const int j0 = blockIdx.x * TILE_J + threadIdx.x * 4;  // first of 4 js for this thread
    const int i0 = blockIdx.y * TILE_I;
    const int row4 = N_ATOMS / 4;
    float4* out4 = reinterpret_cast<float4*>(out);

    // Fast path: tile entirely above the diagonal (min j in tile > max i in tile)
    // -> every entry is masked off -> pure zero store.
    if (blockIdx.x * TILE_J > i0 + TILE_I - 1) {
        const float4 z = make_float4(0.f, 0.f, 0.f, 0.f);
        #pragma unroll 8
        for (int ii = 0; ii < TILE_I; ii++) {
            out4[(size_t)(i0 + ii) * row4 + (j0 >> 2)] = z;
        }
        return;
    }

    __shared__ float4 sI[TILE_I];  // (x, y, z, valid-flag) per i-row of this tile

    if (threadIdx.x < TILE_I) {
        const int i = i0 + threadIdx.x;
        const float iv = (species[i] == -1) ? 0.0f : 1.0f;
        sI[threadIdx.x] = make_float4(coords[3*i + 0], coords[3*i + 1], coords[3*i + 2], iv);
    }

    // Decode cutoff scalar of unknown dtype:
    //  - int32/int64 small positive value (e.g. 5)  -> first word is a small int
    //  - float32 -> bit pattern of any sane cutoff is >= ~1e9 as an int
    const int cbits = *cutoff_raw;
    const float cut = (cbits > 0 && cbits < 1000000) ? (float)cbits
                                                     : __int_as_float(cbits);

    // Per-thread j data (registers)
    float jx[4], jy[4], jz[4], jv[4];
    #pragma unroll
    for (int u = 0; u < 4; u++) {
        const int j = j0 + u;
        jx[u] = coords[3*j + 0];
        jy[u] = coords[3*j + 1];
        jz[u] = coords[3*j + 2];
        jv[u] = (species[j] == -1) ? 0.0f : 1.0f;
    }

    __syncthreads();

    #pragma unroll 4
    for (int ii = 0; ii < TILE_I; ii++) {
        const int i = i0 + ii;
        const float4 ci = sI[ii];
        float r[4];
        #pragma unroll
        for (int u = 0; u < 4; u++) {
            const float dx = ci.x - jx[u];
            const float dy = ci.y - jy[u];
            const float dz = ci.z - jz[u];
            const float sq = dx*dx + dy*dy + dz*dz;
            // Match reference: dist = sqrt(sq > 0 ? sq : 1); mask uses dist <= cutoff.
            const float dist = sqrtf(sq > 0.0f ? sq : 1.0f);
            const bool m = (i > (j0 + u)) & (ci.w != 0.0f) & (jv[u] != 0.0f)
                           & (sq > 0.0f) & (dist <= cut);
            r[u] = m ? dist : 0.0f;
        }
        out4[(size_t)i * row4 + (j0 >> 2)] = make_float4(r[0], r[1], r[2], r[3]);
    }
}

extern "C" void kernel_launch(void* const* d_in, const int* in_sizes, int n_in,
                              void* d_out, int out_size)
{
    const int*   species = (const int*)  d_in[0];  // [1, 6144] int32
    const float* coords  = (const float*)d_in[1];  // [1, 6144, 3] float32
    const int*   cutoff  = (const int*)  d_in[2];  // scalar (int or float bits)

    dim3 grid(N_ATOMS / TILE_J, N_ATOMS / TILE_I);  // 6 x 96 = 576 blocks
    cell_list_kernel<<<grid, THREADS>>>(species, coords, cutoff, (float*)d_out);
}

// round 16
// speedup vs baseline: 1.1718x; 1.1718x over previous
#include <cuda_runtime.h>

#define N_ATOMS 6144
#define TILE_I  32
#define TILE_J  1024
#define THREADS 256

// Dense masked pairwise distance map.
// out[i*N + j] = sqrt(|r_i - r_j|^2)  if  i > j && species_i != -1 && species_j != -1
//                                         && sq > 0 && dist <= cutoff
//              = 0 otherwise.
//
// 1152 blocks (6 x 192), 256 threads; each thread owns 4 consecutive j
// (one float4 streaming store per row iteration -> coalesced 512B/warp).
// Tiles strictly above the diagonal are pure zero-fill (no math, no smem).
__global__ __launch_bounds__(THREADS)
void cell_list_kernel(const int*   __restrict__ species,
                      const float* __restrict__ coords,
                      const int*   __restrict__ cutoff_raw,
                      float*       __restrict__ out)
{
    const int j0 = blockIdx.x * TILE_J + threadIdx.x * 4;  // first of 4 js for this thread
    const int i0 = blockIdx.y * TILE_I;
    const int row4 = N_ATOMS / 4;

    float4* p = reinterpret_cast<float4*>(out) + (size_t)i0 * row4 + (j0 >> 2);

    // Fast path: tile entirely above the diagonal -> pure zero store.
    if (blockIdx.x * TILE_J > i0 + TILE_I - 1) {
        const float4 z = make_float4(0.f, 0.f, 0.f, 0.f);
        #pragma unroll
        for (int ii = 0; ii < TILE_I; ii++) {
            __stcs(p, z);
            p += row4;
        }
        return;
    }

    __shared__ float4 sI[TILE_I];  // (x, y, z, valid-flag) per i-row of this tile

    if (threadIdx.x < TILE_I) {
        const int i = i0 + threadIdx.x;
        const float iv = (species[i] == -1) ? 0.0f : 1.0f;
        sI[threadIdx.x] = make_float4(coords[3*i + 0], coords[3*i + 1], coords[3*i + 2], iv);
    }

    // Decode cutoff scalar of unknown dtype:
    //  - int32/int64 small positive value (e.g. 5)  -> first word is a small int
    //  - float32 -> bit pattern of any sane cutoff is >= ~1e9 as an int
    const int cbits = *cutoff_raw;
    const float cut = (cbits > 0 && cbits < 1000000) ? (float)cbits
                                                     : __int_as_float(cbits);

    // Per-thread j data (registers)
    float jx[4], jy[4], jz[4], jv[4];
    #pragma unroll
    for (int u = 0; u < 4; u++) {
        const int j = j0 + u;
        jx[u] = coords[3*j + 0];
        jy[u] = coords[3*j + 1];
        jz[u] = coords[3*j + 2];
        jv[u] = (species[j] == -1) ? 0.0f : 1.0f;
    }

    __syncthreads();

    #pragma unroll 4
    for (int ii = 0; ii < TILE_I; ii++) {
        const int i = i0 + ii;
        const float4 ci = sI[ii];
        float r[4];
        #pragma unroll
        for (int u = 0; u < 4; u++) {
            const float dx = ci.x - jx[u];
            const float dy = ci.y - jy[u];
            const float dz = ci.z - jz[u];
            const float sq = dx*dx + dy*dy + dz*dz;
            // Match reference: dist = sqrt(sq > 0 ? sq : 1); mask uses dist <= cutoff.
            const float dist = sqrtf(sq > 0.0f ? sq : 1.0f);
            const bool m = (i > (j0 + u)) & (ci.w != 0.0f) & (jv[u] != 0.0f)
                           & (sq > 0.0f) & (dist <= cut);
            r[u] = m ? dist : 0.0f;
        }
        __stcs(p, make_float4(r[0], r[1], r[2], r[3]));
        p += row4;
    }
}

extern "C" void kernel_launch(void* const* d_in, const int* in_sizes, int n_in,
                              void* d_out, int out_size)
{
    const int*   species = (const int*)  d_in[0];  // [1, 6144] int32
    const float* coords  = (const float*)d_in[1];  // [1, 6144, 3] float32
    const int*   cutoff  = (const int*)  d_in[2];  // scalar (int or float bits)

    dim3 grid(N_ATOMS / TILE_J, N_ATOMS / TILE_I);  // 6 x 192 = 1152 blocks
    cell_list_kernel<<<grid, THREADS>>>(species, coords, cutoff, (float*)d_out);
}